// round 16
// baseline (speedup 1.0000x reference)
#include <cuda_runtime.h>
#include <cuda_bf16.h>
#include <cstdint>

typedef unsigned long long ull;

// ---------------- problem constants ----------------
#define BB 32
#define CC 3
#define HH 512
#define WW 512
#define KTOT (CC*HH*WW)
#define NBLK1 768

// ---------------- device scratch ----------------
__device__ float g_partial[160 * NBLK1];
__device__ float g_p[BB * 5];
__device__ __nv_bfloat16 g_FxH[BB * 64 * WW];
__device__ __nv_bfloat16 g_FxL[BB * 64 * WW];
__device__ __nv_bfloat16 g_FyH[BB * 64 * HH];   // gamma folded
__device__ __nv_bfloat16 g_FyL[BB * 64 * HH];
__device__ float g_outP[8][96 * 4096];

// ---------------- helpers ----------------
__device__ __forceinline__ uint32_t smem_u32(const void* p) {
    uint32_t a;
    asm("{ .reg .u64 t; cvta.to.shared.u64 t, %1; cvt.u32.u64 %0, t; }" : "=r"(a) : "l"(p));
    return a;
}
#define SWZ(o) ((o) ^ (((o) >> 3) & 0x70))

__device__ __forceinline__ void cp16(uint32_t dst, const void* src) {
    asm volatile("cp.async.ca.shared.global [%0], [%1], 16;" :: "r"(dst), "l"(src) : "memory");
}
#define CP_COMMIT() asm volatile("cp.async.commit_group;" ::: "memory")
#define CP_WAIT0()  asm volatile("cp.async.wait_group 0;" ::: "memory")

__device__ __forceinline__ void ldsm_x4(uint32_t addr, uint32_t& r0, uint32_t& r1,
                                        uint32_t& r2, uint32_t& r3) {
    asm volatile("ldmatrix.sync.aligned.m8n8.x4.shared.b16 {%0,%1,%2,%3}, [%4];"
                 : "=r"(r0), "=r"(r1), "=r"(r2), "=r"(r3) : "r"(addr));
}
__device__ __forceinline__ void ldsm_x2_t(uint32_t addr, uint32_t& r0, uint32_t& r1) {
    asm volatile("ldmatrix.sync.aligned.m8n8.x2.trans.shared.b16 {%0,%1}, [%2];"
                 : "=r"(r0), "=r"(r1) : "r"(addr));
}
__device__ __forceinline__ void mma_bf16(float* c, const uint32_t* a, const uint32_t* b) {
    asm volatile(
        "mma.sync.aligned.m16n8k16.row.col.f32.bf16.bf16.f32 "
        "{%0,%1,%2,%3}, {%4,%5,%6,%7}, {%8,%9}, {%0,%1,%2,%3};"
        : "+f"(c[0]), "+f"(c[1]), "+f"(c[2]), "+f"(c[3])
        : "r"(a[0]), "r"(a[1]), "r"(a[2]), "r"(a[3]), "r"(b[0]), "r"(b[1]));
}
__device__ __forceinline__ void split4(float4 v, uint2& hv, uint2& lv) {
    __nv_bfloat16 h0 = __float2bfloat16_rn(v.x);
    __nv_bfloat16 h1 = __float2bfloat16_rn(v.y);
    __nv_bfloat16 h2 = __float2bfloat16_rn(v.z);
    __nv_bfloat16 h3 = __float2bfloat16_rn(v.w);
    __nv_bfloat16 l0 = __float2bfloat16_rn(v.x - __bfloat162float(h0));
    __nv_bfloat16 l1 = __float2bfloat16_rn(v.y - __bfloat162float(h1));
    __nv_bfloat16 l2 = __float2bfloat16_rn(v.z - __bfloat162float(h2));
    __nv_bfloat16 l3 = __float2bfloat16_rn(v.w - __bfloat162float(h3));
    hv.x = (uint32_t)__bfloat16_as_ushort(h0) | ((uint32_t)__bfloat16_as_ushort(h1) << 16);
    hv.y = (uint32_t)__bfloat16_as_ushort(h2) | ((uint32_t)__bfloat16_as_ushort(h3) << 16);
    lv.x = (uint32_t)__bfloat16_as_ushort(l0) | ((uint32_t)__bfloat16_as_ushort(l1) << 16);
    lv.y = (uint32_t)__bfloat16_as_ushort(l2) | ((uint32_t)__bfloat16_as_ushort(l3) << 16);
}
__device__ __forceinline__ uint32_t split1(float v, uint32_t& lo16) {
    __nv_bfloat16 hi = __float2bfloat16_rn(v);
    __nv_bfloat16 lo = __float2bfloat16_rn(v - __bfloat162float(hi));
    lo16 = (uint32_t)__bfloat16_as_ushort(lo);
    return (uint32_t)__bfloat16_as_ushort(hi);
}

// ============================================================================
// K1: locnet (R10-proven)
// ============================================================================
__global__ __launch_bounds__(256) void k_locnet(const float* __restrict__ X,
                                                const float* __restrict__ Wl) {
    __shared__ __align__(16) float Wt[5][1028];
    __shared__ float ps[160];
    const int tid = threadIdx.x;
    const int base = blockIdx.x * 1024;
    {
        const float* src = Wl + (size_t)base * 5;
#pragma unroll
        for (int it = 0; it < 5; it++) {
            const int e4 = tid * 4 + it * 1024;
            const float4 v = *(const float4*)&src[e4];
            const float vv[4] = {v.x, v.y, v.z, v.w};
#pragma unroll
            for (int r = 0; r < 4; r++) {
                const int e = e4 + r;
                Wt[e % 5][e / 5] = vv[r];
            }
        }
    }
    __syncthreads();
    const int lane = tid & 31, warp = tid >> 5;
    const int b0 = warp * 4;

    float acc[4][5];
#pragma unroll
    for (int bb = 0; bb < 4; bb++)
#pragma unroll
        for (int j = 0; j < 5; j++) acc[bb][j] = 0.0f;

#pragma unroll
    for (int qi = 0; qi < 4; qi++) {
        const int k = qi * 256 + lane * 4;
        float4 x[4][2];
#pragma unroll
        for (int bb = 0; bb < 4; bb++) {
            const float* Xb = X + (size_t)(b0 + bb) * KTOT + base;
            x[bb][0] = *(const float4*)&Xb[k];
            x[bb][1] = *(const float4*)&Xb[k + 128];
        }
        float4 wv[5][2];
#pragma unroll
        for (int j = 0; j < 5; j++) {
            wv[j][0] = *(const float4*)&Wt[j][k];
            wv[j][1] = *(const float4*)&Wt[j][k + 128];
        }
#pragma unroll
        for (int bb = 0; bb < 4; bb++)
#pragma unroll
            for (int j = 0; j < 5; j++) {
                acc[bb][j] = fmaf(x[bb][0].x, wv[j][0].x, acc[bb][j]);
                acc[bb][j] = fmaf(x[bb][0].y, wv[j][0].y, acc[bb][j]);
                acc[bb][j] = fmaf(x[bb][0].z, wv[j][0].z, acc[bb][j]);
                acc[bb][j] = fmaf(x[bb][0].w, wv[j][0].w, acc[bb][j]);
                acc[bb][j] = fmaf(x[bb][1].x, wv[j][1].x, acc[bb][j]);
                acc[bb][j] = fmaf(x[bb][1].y, wv[j][1].y, acc[bb][j]);
                acc[bb][j] = fmaf(x[bb][1].z, wv[j][1].z, acc[bb][j]);
                acc[bb][j] = fmaf(x[bb][1].w, wv[j][1].w, acc[bb][j]);
            }
    }

#pragma unroll
    for (int bb = 0; bb < 4; bb++)
#pragma unroll
        for (int j = 0; j < 5; j++) {
            float v = acc[bb][j];
#pragma unroll
            for (int off = 16; off > 0; off >>= 1)
                v += __shfl_down_sync(0xffffffffu, v, off);
            if (lane == 0) ps[(b0 + bb) * 5 + j] = v;
        }
    __syncthreads();
    if (tid < 160) g_partial[tid * NBLK1 + blockIdx.x] = ps[tid];
}

__global__ __launch_bounds__(32) void k_reduce_p(const float* __restrict__ b_loc) {
    const int t = blockIdx.x, lane = threadIdx.x;
    const float* src = g_partial + (size_t)t * NBLK1;
    float s = 0.0f;
#pragma unroll
    for (int i = 0; i < NBLK1 / 32; i++) s += src[lane + i * 32];
#pragma unroll
    for (int off = 16; off > 0; off >>= 1)
        s += __shfl_down_sync(0xffffffffu, s, off);
    if (lane == 0) g_p[t] = s + b_loc[t % 5];
}

// ============================================================================
// K2: filter banks — Fx and Fy as bf16 hi/lo planes (R13-proven)
// ============================================================================
__global__ __launch_bounds__(128) void k_filters() {
    const int n = blockIdx.x, axis = blockIdx.y, b = blockIdx.z;
    const int tid = threadIdx.x;
    const float* pb = g_p + b * 5;
    const float sigma2 = expf(pb[2]);
    const float delta = expf(pb[3]) * (511.0f / 63.0f);
    const float gctr = (axis == 0) ? 32.0f * (pb[0] + 1.0f) : 32.0f * (pb[1] + 1.0f);
    const float m = gctr + delta * ((float)n - 32.5f);
    const float inv2s = 1.0f / (2.0f * sigma2);
    float vals[4], lsum = 0.0f;
#pragma unroll
    for (int i = 0; i < 4; i++) {
        const float a = (float)(tid + i * 128);
        const float d = a - m;
        const float e = expf(-d * d * inv2s);
        vals[i] = e; lsum += e;
    }
    __shared__ float sw[4];
#pragma unroll
    for (int off = 16; off > 0; off >>= 1)
        lsum += __shfl_down_sync(0xffffffffu, lsum, off);
    if ((tid & 31) == 0) sw[tid >> 5] = lsum;
    __syncthreads();
    const float tot = sw[0] + sw[1] + sw[2] + sw[3];
    float scale = 1.0f / (tot + 1e-4f);
    if (axis == 1) scale *= expf(pb[4]);

    const size_t rowoff = ((size_t)b * 64 + n) * 512;
    __nv_bfloat16* dH = (axis == 0) ? g_FxH : g_FyH;
    __nv_bfloat16* dL = (axis == 0) ? g_FxL : g_FyL;
#pragma unroll
    for (int i = 0; i < 4; i++) {
        const float v = vals[i] * scale;
        const __nv_bfloat16 hi = __float2bfloat16_rn(v);
        const __nv_bfloat16 lo = __float2bfloat16_rn(v - __bfloat162float(hi));
        dH[rowoff + tid + i * 128] = hi;
        dL[rowoff + tid + i * 128] = lo;
    }
}

// ============================================================================
// K3: fused GEMM1+GEMM2, 64h x 64m tiles, 3 CTAs/SM.
// Mainloop: chunk 64 w, SW128, double-buffered 2x32K, F via cp.async.
// Warp tile: 16h x 32m (4 h-strips x 2 m-halves).
// Epilogue: Gx -> bf16 hi/lo [64][72]; Fy hi/lo [64][72]; K=64 tensor GEMM2.
// grid (8 ht, 3 c, 32 b) = 768 CTAs.
// ============================================================================
#define PBUF 32768       // XH 8K | XL 8K | FH 8K | FL 8K
#define GEMM1_DYN (2 * PBUF)
// epilogue smem byte offsets ([64][72] bf16 = 9216 B each)
#define EGXH 0
#define EGXL 9216
#define EFYH 18432
#define EFYL 27648

__global__ __launch_bounds__(256, 3) void k_gemm1_fused(const float* __restrict__ X) {
    extern __shared__ __align__(1024) char smem[];
    const uint32_t sbase = smem_u32(smem);

    const int tid = threadIdx.x;
    const int wid = tid >> 5, lane = tid & 31;
    const int ht = blockIdx.x, c = blockIdx.y, b = blockIdx.z;
    const int h0 = ht * 64;
    const float* Xbc = X + (((size_t)b * CC + c) * HH + h0) * WW;
    const __nv_bfloat16* FxbH = g_FxH + (size_t)b * 64 * 512;
    const __nv_bfloat16* FxbL = g_FxL + (size_t)b * 64 * 512;

    float acc[4][4];
#pragma unroll
    for (int nt = 0; nt < 4; nt++)
#pragma unroll
        for (int r = 0; r < 4; r++) acc[nt][r] = 0.0f;

    // X geometry: 64 rows x 64 w per chunk; thread -> row tid>>4 (+p*16), col (tid&15)*4
    const int xRow = tid >> 4;
    const int xC4 = (tid & 15) * 4;
    // F cp.async geometry: 64 rows x 128B; thread -> row tid>>2, 2 x 16B segs
    const int fM = tid >> 2;
    const int fS0 = (tid & 3) * 2;
    // mainloop ldsm geometry: warp tile 16h x 32m
    const int aRow = (wid & 3) * 16 + (lane & 15);
    const int aK8 = (lane >> 4) * 8;
    const int m0w = (wid >> 2) * 32;
    const int bN = m0w + ((lane >> 4) << 3) + (lane & 7);
    const int bK8 = ((lane >> 3) & 1) * 8;

    float4 xr[4];

#define LOADX(w0)                                                               \
    do {                                                                        \
        _Pragma("unroll")                                                       \
        for (int p = 0; p < 4; p++)                                             \
            xr[p] = *(const float4*)&Xbc[(xRow + p * 16) * 512 + (w0) + xC4];   \
    } while (0)

#define CPF(w0, bufU)                                                           \
    do {                                                                        \
        _Pragma("unroll")                                                       \
        for (int s = 0; s < 2; s++) {                                           \
            const uint32_t so = SWZ((uint32_t)(fM * 128 + (fS0 + s) * 16));     \
            cp16((bufU) + 16384 + so, FxbH + fM * 512 + (w0) + (fS0 + s) * 8);  \
            cp16((bufU) + 24576 + so, FxbL + fM * 512 + (w0) + (fS0 + s) * 8);  \
        }                                                                       \
        CP_COMMIT();                                                            \
    } while (0)

#define STOREX(bufP)                                                            \
    do {                                                                        \
        _Pragma("unroll")                                                       \
        for (int p = 0; p < 4; p++) {                                           \
            uint2 hv, lv;                                                       \
            split4(xr[p], hv, lv);                                              \
            const uint32_t so = SWZ((uint32_t)((xRow + p * 16) * 128 + xC4 * 2)); \
            *(uint2*)((bufP) + so) = hv;                                        \
            *(uint2*)((bufP) + 8192 + so) = lv;                                 \
        }                                                                       \
    } while (0)

    CPF(0, sbase);
    LOADX(0);
    STOREX(smem);
    CP_WAIT0();
    __syncthreads();

    for (int ch = 0; ch < 8; ch++) {
        const uint32_t bufU = sbase + (ch & 1) * PBUF;
        const uint32_t nbufU = sbase + ((ch + 1) & 1) * PBUF;

        if (ch < 7) {
            CPF((ch + 1) * 64, nbufU);
            LOADX((ch + 1) * 64);
        }

        const uint32_t XH = bufU, XL = bufU + 8192;
        const uint32_t FH = bufU + 16384, FL = bufU + 24576;

#pragma unroll
        for (int kc = 0; kc < 64; kc += 16) {
            uint32_t ah[4], al[4];
            {
                const uint32_t off = SWZ((uint32_t)(aRow * 128 + (kc + aK8) * 2));
                ldsm_x4(XH + off, ah[0], ah[1], ah[2], ah[3]);
                ldsm_x4(XL + off, al[0], al[1], al[2], al[3]);
            }
            uint32_t bh[8], bl[8];
#pragma unroll
            for (int nb = 0; nb < 2; nb++) {
                const uint32_t off = SWZ(
                    (uint32_t)((bN + nb * 16) * 128 + (kc + bK8) * 2));
                ldsm_x4(FH + off, bh[nb * 4 + 0], bh[nb * 4 + 1],
                        bh[nb * 4 + 2], bh[nb * 4 + 3]);
                ldsm_x4(FL + off, bl[nb * 4 + 0], bl[nb * 4 + 1],
                        bl[nb * 4 + 2], bl[nb * 4 + 3]);
            }
#pragma unroll
            for (int nt = 0; nt < 4; nt++) {
                float* a = acc[nt];
                mma_bf16(a, ah, &bh[nt * 2]);
                mma_bf16(a, ah, &bl[nt * 2]);
                mma_bf16(a, al, &bh[nt * 2]);
            }
        }

        if (ch < 7) {
            char* nb = smem + ((ch + 1) & 1) * PBUF;
            STOREX(nb);
        }
        CP_WAIT0();
        __syncthreads();
    }
#undef LOADX
#undef CPF
#undef STOREX

    // ======================= tensor epilogue (GEMM2 partial) ================
    // 1) Gx acc -> bf16 hi/lo planes in smem: [64h][72]
    {
        const int r0e = (wid & 3) * 16 + (lane >> 2);
        const int c0e = (lane & 3) * 2;
#pragma unroll
        for (int nt = 0; nt < 4; nt++) {
            const int m = m0w + nt * 8 + c0e;
            uint32_t lo0, lo1, lo2, lo3;
            const uint32_t h00 = split1(acc[nt][0], lo0);
            const uint32_t h01 = split1(acc[nt][1], lo1);
            const uint32_t h10 = split1(acc[nt][2], lo2);
            const uint32_t h11 = split1(acc[nt][3], lo3);
            *(uint32_t*)(smem + EGXH + ((r0e + 0) * 72 + m) * 2) = h00 | (h01 << 16);
            *(uint32_t*)(smem + EGXL + ((r0e + 0) * 72 + m) * 2) = lo0 | (lo1 << 16);
            *(uint32_t*)(smem + EGXH + ((r0e + 8) * 72 + m) * 2) = h10 | (h11 << 16);
            *(uint32_t*)(smem + EGXL + ((r0e + 8) * 72 + m) * 2) = lo2 | (lo3 << 16);
        }
    }
    // 2) stage Fy hi/lo tile: [64n][72] (64 h + pad)
    {
        const int n = tid >> 2;
        const int co = (tid & 3) * 16;
        const __nv_bfloat16* FyHg = g_FyH + ((size_t)b * 64 + n) * 512 + h0 + co;
        const __nv_bfloat16* FyLg = g_FyL + ((size_t)b * 64 + n) * 512 + h0 + co;
#pragma unroll
        for (int q = 0; q < 2; q++) {
            *(uint4*)(smem + EFYH + (n * 72 + co + q * 8) * 2) =
                *(const uint4*)&FyHg[q * 8];
            *(uint4*)(smem + EFYL + (n * 72 + co + q * 8) * 2) =
                *(const uint4*)&FyLg[q * 8];
        }
    }
    __syncthreads();

    // 3) mma: warp w -> n-strip (w&3)*16, m-half (w>>2)*32, K=64
    {
        const int n0 = (wid & 3) * 16;
        const int m0 = (wid >> 2) * 32;
        const int aRowE = n0 + (lane & 15);
        const int aK8E = (lane >> 4) * 8;
        const int bK = lane & 15;

        float acc_e[4][4];
#pragma unroll
        for (int j = 0; j < 4; j++)
#pragma unroll
            for (int r = 0; r < 4; r++) acc_e[j][r] = 0.0f;

#pragma unroll
        for (int kc = 0; kc < 64; kc += 16) {
            uint32_t ah[4], al[4];
            ldsm_x4(sbase + EFYH + (aRowE * 72 + kc + aK8E) * 2,
                    ah[0], ah[1], ah[2], ah[3]);
            ldsm_x4(sbase + EFYL + (aRowE * 72 + kc + aK8E) * 2,
                    al[0], al[1], al[2], al[3]);
#pragma unroll
            for (int j = 0; j < 4; j++) {
                uint32_t bh[2], bl[2];
                const uint32_t boff = ((kc + bK) * 72 + m0 + j * 8) * 2;
                ldsm_x2_t(sbase + EGXH + boff, bh[0], bh[1]);
                ldsm_x2_t(sbase + EGXL + boff, bl[0], bl[1]);
                mma_bf16(acc_e[j], ah, bh);
                mma_bf16(acc_e[j], ah, bl);
                mma_bf16(acc_e[j], al, bh);
            }
        }

        float* O = g_outP[ht] + ((size_t)b * CC + c) * 4096;
        const int nr = n0 + (lane >> 2);
        const int mc = (lane & 3) * 2;
#pragma unroll
        for (int j = 0; j < 4; j++) {
            *(float2*)&O[(nr + 0) * 64 + m0 + j * 8 + mc] =
                make_float2(acc_e[j][0], acc_e[j][1]);
            *(float2*)&O[(nr + 8) * 64 + m0 + j * 8 + mc] =
                make_float2(acc_e[j][2], acc_e[j][3]);
        }
    }
}

// K5: sum the 8 h-split partials
__global__ __launch_bounds__(256) void k_sumout(float* __restrict__ out) {
    const int i4 = (blockIdx.x * 256 + threadIdx.x) * 4;
    float4 s = *(const float4*)&g_outP[0][i4];
#pragma unroll
    for (int p = 1; p < 8; p++) {
        const float4 v = *(const float4*)&g_outP[p][i4];
        s.x += v.x; s.y += v.y; s.z += v.z; s.w += v.w;
    }
    *(float4*)&out[i4] = s;
}

// ============================================================================
extern "C" void kernel_launch(void* const* d_in, const int* in_sizes, int n_in,
                              void* d_out, int out_size) {
    (void)in_sizes; (void)n_in; (void)out_size;
    const float* X    = (const float*)d_in[0];
    const float* Wl   = (const float*)d_in[1];
    const float* bloc = (const float*)d_in[2];
    float* out = (float*)d_out;

    static int attr_set = 0;
    if (!attr_set) {
        cudaFuncSetAttribute(k_gemm1_fused,
                             cudaFuncAttributeMaxDynamicSharedMemorySize, GEMM1_DYN);
        attr_set = 1;
    }

    k_locnet<<<NBLK1, 256>>>(X, Wl);
    k_reduce_p<<<160, 32>>>(bloc);
    k_filters<<<dim3(64, 2, 32), 128>>>();
    k_gemm1_fused<<<dim3(8, 3, 32), 256, GEMM1_DYN>>>(X);
    k_sumout<<<384, 256>>>(out);
}

// round 17
// speedup vs baseline: 1.0991x; 1.0991x over previous
#include <cuda_runtime.h>
#include <cuda_bf16.h>
#include <cstdint>

typedef unsigned long long ull;

// ---------------- problem constants ----------------
#define BB 32
#define CC 3
#define HH 512
#define WW 512
#define KTOT (CC*HH*WW)
#define NBLK1 768

// ---------------- device scratch ----------------
__device__ float g_partial[160 * NBLK1];
__device__ float g_p[BB * 5];
__device__ __nv_bfloat16 g_FxH[BB * 64 * WW];
__device__ __nv_bfloat16 g_FxL[BB * 64 * WW];
__device__ __nv_bfloat16 g_FyH[BB * 64 * HH];   // gamma folded
__device__ __nv_bfloat16 g_FyL[BB * 64 * HH];
__device__ float g_outP[4][96 * 4096];

// ---------------- helpers ----------------
__device__ __forceinline__ uint32_t smem_u32(const void* p) {
    uint32_t a;
    asm("{ .reg .u64 t; cvta.to.shared.u64 t, %1; cvt.u32.u64 %0, t; }" : "=r"(a) : "l"(p));
    return a;
}
#define SWZ(o) ((o) ^ (((o) >> 3) & 0x70))

__device__ __forceinline__ void cp16(uint32_t dst, const void* src) {
    asm volatile("cp.async.ca.shared.global [%0], [%1], 16;" :: "r"(dst), "l"(src) : "memory");
}
#define CP_COMMIT() asm volatile("cp.async.commit_group;" ::: "memory")
#define CP_WAIT0()  asm volatile("cp.async.wait_group 0;" ::: "memory")

__device__ __forceinline__ void ldsm_x4(uint32_t addr, uint32_t& r0, uint32_t& r1,
                                        uint32_t& r2, uint32_t& r3) {
    asm volatile("ldmatrix.sync.aligned.m8n8.x4.shared.b16 {%0,%1,%2,%3}, [%4];"
                 : "=r"(r0), "=r"(r1), "=r"(r2), "=r"(r3) : "r"(addr));
}
__device__ __forceinline__ void ldsm_x2_t(uint32_t addr, uint32_t& r0, uint32_t& r1) {
    asm volatile("ldmatrix.sync.aligned.m8n8.x2.trans.shared.b16 {%0,%1}, [%2];"
                 : "=r"(r0), "=r"(r1) : "r"(addr));
}
__device__ __forceinline__ void mma_bf16(float* c, const uint32_t* a, const uint32_t* b) {
    asm volatile(
        "mma.sync.aligned.m16n8k16.row.col.f32.bf16.bf16.f32 "
        "{%0,%1,%2,%3}, {%4,%5,%6,%7}, {%8,%9}, {%0,%1,%2,%3};"
        : "+f"(c[0]), "+f"(c[1]), "+f"(c[2]), "+f"(c[3])
        : "r"(a[0]), "r"(a[1]), "r"(a[2]), "r"(a[3]), "r"(b[0]), "r"(b[1]));
}
__device__ __forceinline__ void split4(float4 v, uint2& hv, uint2& lv) {
    __nv_bfloat16 h0 = __float2bfloat16_rn(v.x);
    __nv_bfloat16 h1 = __float2bfloat16_rn(v.y);
    __nv_bfloat16 h2 = __float2bfloat16_rn(v.z);
    __nv_bfloat16 h3 = __float2bfloat16_rn(v.w);
    __nv_bfloat16 l0 = __float2bfloat16_rn(v.x - __bfloat162float(h0));
    __nv_bfloat16 l1 = __float2bfloat16_rn(v.y - __bfloat162float(h1));
    __nv_bfloat16 l2 = __float2bfloat16_rn(v.z - __bfloat162float(h2));
    __nv_bfloat16 l3 = __float2bfloat16_rn(v.w - __bfloat162float(h3));
    hv.x = (uint32_t)__bfloat16_as_ushort(h0) | ((uint32_t)__bfloat16_as_ushort(h1) << 16);
    hv.y = (uint32_t)__bfloat16_as_ushort(h2) | ((uint32_t)__bfloat16_as_ushort(h3) << 16);
    lv.x = (uint32_t)__bfloat16_as_ushort(l0) | ((uint32_t)__bfloat16_as_ushort(l1) << 16);
    lv.y = (uint32_t)__bfloat16_as_ushort(l2) | ((uint32_t)__bfloat16_as_ushort(l3) << 16);
}
__device__ __forceinline__ uint32_t split1(float v, uint32_t& lo16) {
    __nv_bfloat16 hi = __float2bfloat16_rn(v);
    __nv_bfloat16 lo = __float2bfloat16_rn(v - __bfloat162float(hi));
    lo16 = (uint32_t)__bfloat16_as_ushort(lo);
    return (uint32_t)__bfloat16_as_ushort(hi);
}

// ============================================================================
// K1: locnet (R10-proven)
// ============================================================================
__global__ __launch_bounds__(256) void k_locnet(const float* __restrict__ X,
                                                const float* __restrict__ Wl) {
    __shared__ __align__(16) float Wt[5][1028];
    __shared__ float ps[160];
    const int tid = threadIdx.x;
    const int base = blockIdx.x * 1024;
    {
        const float* src = Wl + (size_t)base * 5;
#pragma unroll
        for (int it = 0; it < 5; it++) {
            const int e4 = tid * 4 + it * 1024;
            const float4 v = *(const float4*)&src[e4];
            const float vv[4] = {v.x, v.y, v.z, v.w};
#pragma unroll
            for (int r = 0; r < 4; r++) {
                const int e = e4 + r;
                Wt[e % 5][e / 5] = vv[r];
            }
        }
    }
    __syncthreads();
    const int lane = tid & 31, warp = tid >> 5;
    const int b0 = warp * 4;

    float acc[4][5];
#pragma unroll
    for (int bb = 0; bb < 4; bb++)
#pragma unroll
        for (int j = 0; j < 5; j++) acc[bb][j] = 0.0f;

#pragma unroll
    for (int qi = 0; qi < 4; qi++) {
        const int k = qi * 256 + lane * 4;
        float4 x[4][2];
#pragma unroll
        for (int bb = 0; bb < 4; bb++) {
            const float* Xb = X + (size_t)(b0 + bb) * KTOT + base;
            x[bb][0] = *(const float4*)&Xb[k];
            x[bb][1] = *(const float4*)&Xb[k + 128];
        }
        float4 wv[5][2];
#pragma unroll
        for (int j = 0; j < 5; j++) {
            wv[j][0] = *(const float4*)&Wt[j][k];
            wv[j][1] = *(const float4*)&Wt[j][k + 128];
        }
#pragma unroll
        for (int bb = 0; bb < 4; bb++)
#pragma unroll
            for (int j = 0; j < 5; j++) {
                acc[bb][j] = fmaf(x[bb][0].x, wv[j][0].x, acc[bb][j]);
                acc[bb][j] = fmaf(x[bb][0].y, wv[j][0].y, acc[bb][j]);
                acc[bb][j] = fmaf(x[bb][0].z, wv[j][0].z, acc[bb][j]);
                acc[bb][j] = fmaf(x[bb][0].w, wv[j][0].w, acc[bb][j]);
                acc[bb][j] = fmaf(x[bb][1].x, wv[j][1].x, acc[bb][j]);
                acc[bb][j] = fmaf(x[bb][1].y, wv[j][1].y, acc[bb][j]);
                acc[bb][j] = fmaf(x[bb][1].z, wv[j][1].z, acc[bb][j]);
                acc[bb][j] = fmaf(x[bb][1].w, wv[j][1].w, acc[bb][j]);
            }
    }

#pragma unroll
    for (int bb = 0; bb < 4; bb++)
#pragma unroll
        for (int j = 0; j < 5; j++) {
            float v = acc[bb][j];
#pragma unroll
            for (int off = 16; off > 0; off >>= 1)
                v += __shfl_down_sync(0xffffffffu, v, off);
            if (lane == 0) ps[(b0 + bb) * 5 + j] = v;
        }
    __syncthreads();
    if (tid < 160) g_partial[tid * NBLK1 + blockIdx.x] = ps[tid];
}

__global__ __launch_bounds__(32) void k_reduce_p(const float* __restrict__ b_loc) {
    const int t = blockIdx.x, lane = threadIdx.x;
    const float* src = g_partial + (size_t)t * NBLK1;
    float s = 0.0f;
#pragma unroll
    for (int i = 0; i < NBLK1 / 32; i++) s += src[lane + i * 32];
#pragma unroll
    for (int off = 16; off > 0; off >>= 1)
        s += __shfl_down_sync(0xffffffffu, s, off);
    if (lane == 0) g_p[t] = s + b_loc[t % 5];
}

// ============================================================================
// K2: filter banks — Fx and Fy as bf16 hi/lo planes (R13-proven)
// ============================================================================
__global__ __launch_bounds__(128) void k_filters() {
    const int n = blockIdx.x, axis = blockIdx.y, b = blockIdx.z;
    const int tid = threadIdx.x;
    const float* pb = g_p + b * 5;
    const float sigma2 = expf(pb[2]);
    const float delta = expf(pb[3]) * (511.0f / 63.0f);
    const float gctr = (axis == 0) ? 32.0f * (pb[0] + 1.0f) : 32.0f * (pb[1] + 1.0f);
    const float m = gctr + delta * ((float)n - 32.5f);
    const float inv2s = 1.0f / (2.0f * sigma2);
    float vals[4], lsum = 0.0f;
#pragma unroll
    for (int i = 0; i < 4; i++) {
        const float a = (float)(tid + i * 128);
        const float d = a - m;
        const float e = expf(-d * d * inv2s);
        vals[i] = e; lsum += e;
    }
    __shared__ float sw[4];
#pragma unroll
    for (int off = 16; off > 0; off >>= 1)
        lsum += __shfl_down_sync(0xffffffffu, lsum, off);
    if ((tid & 31) == 0) sw[tid >> 5] = lsum;
    __syncthreads();
    const float tot = sw[0] + sw[1] + sw[2] + sw[3];
    float scale = 1.0f / (tot + 1e-4f);
    if (axis == 1) scale *= expf(pb[4]);

    const size_t rowoff = ((size_t)b * 64 + n) * 512;
    __nv_bfloat16* dH = (axis == 0) ? g_FxH : g_FyH;
    __nv_bfloat16* dL = (axis == 0) ? g_FxL : g_FyL;
#pragma unroll
    for (int i = 0; i < 4; i++) {
        const float v = vals[i] * scale;
        const __nv_bfloat16 hi = __float2bfloat16_rn(v);
        const __nv_bfloat16 lo = __float2bfloat16_rn(v - __bfloat162float(hi));
        dH[rowoff + tid + i * 128] = hi;
        dL[rowoff + tid + i * 128] = lo;
    }
}

// ============================================================================
// K3: fused GEMM1+GEMM2, 128h x 64m, 3 CTAs/SM SINGLE WAVE (384 <= 444).
// X single-buffered (convert phase after MMA), F double-buffered via cp.async.
// smem = 64K: XH 16K | XL 16K | FH0 8K | FL0 8K | FH1 8K | FL1 8K.
// Epilogue (tensor GEMM2) in two 64-h passes within 36.8K.
// ============================================================================
#define GEMM1_DYN 65536
// epilogue smem byte offsets ([64][72] bf16 = 9216 B each)
#define EGXH 0
#define EGXL 9216
#define EFYH 18432
#define EFYL 27648

__global__ __launch_bounds__(256, 3) void k_gemm1_fused(const float* __restrict__ X) {
    extern __shared__ __align__(1024) char smem[];
    const uint32_t sbase = smem_u32(smem);

    const int tid = threadIdx.x;
    const int wid = tid >> 5, lane = tid & 31;
    const int ht = blockIdx.x, c = blockIdx.y, b = blockIdx.z;
    const int h0 = ht * 128;
    const float* Xbc = X + (((size_t)b * CC + c) * HH + h0) * WW;
    const __nv_bfloat16* FxbH = g_FxH + (size_t)b * 64 * 512;
    const __nv_bfloat16* FxbL = g_FxL + (size_t)b * 64 * 512;

    float acc[8][4];
#pragma unroll
    for (int nt = 0; nt < 8; nt++)
#pragma unroll
        for (int r = 0; r < 4; r++) acc[nt][r] = 0.0f;

    // X convert geometry: thread -> row tid>>4 (+p*16), col (tid&15)*4
    const int xRow = tid >> 4;
    const int xC4 = (tid & 15) * 4;
    // F cp.async geometry
    const int fM = tid >> 2;
    const int fS0 = (tid & 3) * 2;
    // mainloop ldsm geometry (R13/R15-proven)
    const int aRow = wid * 16 + (lane & 15);
    const int aK8 = (lane >> 4) * 8;
    const int bN = ((lane >> 4) << 3) + (lane & 7);
    const int bK8 = ((lane >> 3) & 1) * 8;

    // convert + store one X chunk into the single X buffer (loads inline;
    // ptxas batches the 8 independent LDG.128 for MLP)
#define CONVX(w0)                                                               \
    do {                                                                        \
        _Pragma("unroll")                                                       \
        for (int p = 0; p < 8; p++) {                                           \
            const float4 v =                                                    \
                *(const float4*)&Xbc[(xRow + p * 16) * 512 + (w0) + xC4];       \
            uint2 hv, lv;                                                       \
            split4(v, hv, lv);                                                  \
            const uint32_t so = SWZ((uint32_t)((xRow + p * 16) * 128 + xC4 * 2)); \
            *(uint2*)(smem + so) = hv;                                          \
            *(uint2*)(smem + 16384 + so) = lv;                                  \
        }                                                                       \
    } while (0)

#define CPF(w0, fbase)                                                          \
    do {                                                                        \
        _Pragma("unroll")                                                       \
        for (int s = 0; s < 2; s++) {                                           \
            const uint32_t so = SWZ((uint32_t)(fM * 128 + (fS0 + s) * 16));     \
            cp16((fbase) + so, FxbH + fM * 512 + (w0) + (fS0 + s) * 8);         \
            cp16((fbase) + 8192 + so, FxbL + fM * 512 + (w0) + (fS0 + s) * 8);  \
        }                                                                       \
        CP_COMMIT();                                                            \
    } while (0)

    // prologue: F chunk 0 -> F0, X chunk 0 -> X buffer
    CPF(0, sbase + 32768);
    CONVX(0);
    CP_WAIT0();
    __syncthreads();

    for (int ch = 0; ch < 8; ch++) {
        // fire next F chunk into the other F buffer (lands during MMA)
        if (ch < 7) CPF((ch + 1) * 64, sbase + 32768 + ((ch + 1) & 1) * 16384);

        const uint32_t XH = sbase, XL = sbase + 16384;
        const uint32_t FH = sbase + 32768 + (ch & 1) * 16384;
        const uint32_t FL = FH + 8192;

#pragma unroll
        for (int kc = 0; kc < 64; kc += 16) {
            uint32_t ah[4], al[4];
            {
                const uint32_t off = SWZ((uint32_t)(aRow * 128 + (kc + aK8) * 2));
                ldsm_x4(XH + off, ah[0], ah[1], ah[2], ah[3]);
                ldsm_x4(XL + off, al[0], al[1], al[2], al[3]);
            }
#pragma unroll
            for (int half = 0; half < 2; half++) {
                uint32_t bh[8], bl[8];
#pragma unroll
                for (int nb = 0; nb < 2; nb++) {
                    const uint32_t off = SWZ(
                        (uint32_t)((bN + (half * 2 + nb) * 16) * 128 + (kc + bK8) * 2));
                    ldsm_x4(FH + off, bh[nb * 4 + 0], bh[nb * 4 + 1],
                            bh[nb * 4 + 2], bh[nb * 4 + 3]);
                    ldsm_x4(FL + off, bl[nb * 4 + 0], bl[nb * 4 + 1],
                            bl[nb * 4 + 2], bl[nb * 4 + 3]);
                }
#pragma unroll
                for (int nt = 0; nt < 4; nt++) {
                    float* a = acc[half * 4 + nt];
                    mma_bf16(a, ah, &bh[nt * 2]);
                    mma_bf16(a, ah, &bl[nt * 2]);
                    mma_bf16(a, al, &bh[nt * 2]);
                }
            }
        }
        __syncthreads();                    // everyone done reading X buffer

        if (ch < 7) CONVX((ch + 1) * 64);   // refill single X buffer
        CP_WAIT0();                         // F(ch+1) landed long ago
        __syncthreads();
    }
#undef CONVX
#undef CPF

    // ============== tensor epilogue (GEMM2 partial), two 64-h passes ========
    const int n0 = (wid & 3) * 16;
    const int m0 = (wid >> 2) * 32;
    float acc_e[4][4];
#pragma unroll
    for (int j = 0; j < 4; j++)
#pragma unroll
        for (int r = 0; r < 4; r++) acc_e[j][r] = 0.0f;

#pragma unroll
    for (int hp = 0; hp < 2; hp++) {
        // 1) Gx acc rows [hp*64, hp*64+64) -> bf16 hi/lo smem [64][72]
        if ((wid >> 2) == hp) {
            const int r0e = (wid & 3) * 16 + (lane >> 2);   // local row in pass
            const int c0e = (lane & 3) * 2;
#pragma unroll
            for (int nt = 0; nt < 8; nt++) {
                const int m = nt * 8 + c0e;
                uint32_t lo0, lo1, lo2, lo3;
                const uint32_t h00 = split1(acc[nt][0], lo0);
                const uint32_t h01 = split1(acc[nt][1], lo1);
                const uint32_t h10 = split1(acc[nt][2], lo2);
                const uint32_t h11 = split1(acc[nt][3], lo3);
                *(uint32_t*)(smem + EGXH + ((r0e + 0) * 72 + m) * 2) = h00 | (h01 << 16);
                *(uint32_t*)(smem + EGXL + ((r0e + 0) * 72 + m) * 2) = lo0 | (lo1 << 16);
                *(uint32_t*)(smem + EGXH + ((r0e + 8) * 72 + m) * 2) = h10 | (h11 << 16);
                *(uint32_t*)(smem + EGXL + ((r0e + 8) * 72 + m) * 2) = lo2 | (lo3 << 16);
            }
        }
        // 2) stage Fy hi/lo tile for this h-half: [64n][72]
        {
            const int n = tid >> 2;
            const int co = (tid & 3) * 16;
            const __nv_bfloat16* FyHg =
                g_FyH + ((size_t)b * 64 + n) * 512 + h0 + hp * 64 + co;
            const __nv_bfloat16* FyLg =
                g_FyL + ((size_t)b * 64 + n) * 512 + h0 + hp * 64 + co;
#pragma unroll
            for (int q = 0; q < 2; q++) {
                *(uint4*)(smem + EFYH + (n * 72 + co + q * 8) * 2) =
                    *(const uint4*)&FyHg[q * 8];
                *(uint4*)(smem + EFYL + (n * 72 + co + q * 8) * 2) =
                    *(const uint4*)&FyLg[q * 8];
            }
        }
        __syncthreads();

        // 3) mma over this half's K=64, accumulate across passes
        {
            const int aRowE = n0 + (lane & 15);
            const int aK8E = (lane >> 4) * 8;
            const int bK = lane & 15;
#pragma unroll
            for (int kc = 0; kc < 64; kc += 16) {
                uint32_t ah[4], al[4];
                ldsm_x4(sbase + EFYH + (aRowE * 72 + kc + aK8E) * 2,
                        ah[0], ah[1], ah[2], ah[3]);
                ldsm_x4(sbase + EFYL + (aRowE * 72 + kc + aK8E) * 2,
                        al[0], al[1], al[2], al[3]);
#pragma unroll
                for (int j = 0; j < 4; j++) {
                    uint32_t bh[2], bl[2];
                    const uint32_t boff = ((kc + bK) * 72 + m0 + j * 8) * 2;
                    ldsm_x2_t(sbase + EGXH + boff, bh[0], bh[1]);
                    ldsm_x2_t(sbase + EGXL + boff, bl[0], bl[1]);
                    mma_bf16(acc_e[j], ah, bh);
                    mma_bf16(acc_e[j], ah, bl);
                    mma_bf16(acc_e[j], al, bh);
                }
            }
        }
        __syncthreads();
    }

    // write the per-ht partial
    {
        float* O = g_outP[ht] + ((size_t)b * CC + c) * 4096;
        const int nr = n0 + (lane >> 2);
        const int mc = (lane & 3) * 2;
#pragma unroll
        for (int j = 0; j < 4; j++) {
            *(float2*)&O[(nr + 0) * 64 + m0 + j * 8 + mc] =
                make_float2(acc_e[j][0], acc_e[j][1]);
            *(float2*)&O[(nr + 8) * 64 + m0 + j * 8 + mc] =
                make_float2(acc_e[j][2], acc_e[j][3]);
        }
    }
}

// K5: sum the 4 h-split partials
__global__ __launch_bounds__(256) void k_sumout(float* __restrict__ out) {
    const int i4 = (blockIdx.x * 256 + threadIdx.x) * 4;
    const float4 a = *(const float4*)&g_outP[0][i4];
    const float4 b = *(const float4*)&g_outP[1][i4];
    const float4 c = *(const float4*)&g_outP[2][i4];
    const float4 d = *(const float4*)&g_outP[3][i4];
    *(float4*)&out[i4] = make_float4(a.x + b.x + c.x + d.x, a.y + b.y + c.y + d.y,
                                     a.z + b.z + c.z + d.z, a.w + b.w + c.w + d.w);
}

// ============================================================================
extern "C" void kernel_launch(void* const* d_in, const int* in_sizes, int n_in,
                              void* d_out, int out_size) {
    (void)in_sizes; (void)n_in; (void)out_size;
    const float* X    = (const float*)d_in[0];
    const float* Wl   = (const float*)d_in[1];
    const float* bloc = (const float*)d_in[2];
    float* out = (float*)d_out;

    static int attr_set = 0;
    if (!attr_set) {
        cudaFuncSetAttribute(k_gemm1_fused,
                             cudaFuncAttributeMaxDynamicSharedMemorySize, GEMM1_DYN);
        attr_set = 1;
    }

    k_locnet<<<NBLK1, 256>>>(X, Wl);
    k_reduce_p<<<160, 32>>>(bloc);
    k_filters<<<dim3(64, 2, 32), 128>>>();
    k_gemm1_fused<<<dim3(4, 3, 32), 256, GEMM1_DYN>>>(X);
    k_sumout<<<384, 256>>>(out);
}